// round 3
// baseline (speedup 1.0000x reference)
#include <cuda_runtime.h>
#include <cstdint>

#define NQ     8
#define DIM    256
#define NW     16
#define BATCH  16
#define NROTS  64
#define EMB    512
#define VOCAB  50257
#define NM     24

typedef unsigned long long ull;

/* ---------------- scratch (device globals; no allocation allowed) -------- */
__device__ float g_fp[BATCH];
__device__ float g_h[BATCH * EMB];

/* ---------------- packed f32x2 helpers ----------------------------------- */
__device__ __forceinline__ ull fma2(ull a, ull b, ull c) {
    ull d;
    asm("fma.rn.f32x2 %0, %1, %2, %3;" : "=l"(d) : "l"(a), "l"(b), "l"(c));
    return d;
}
__device__ __forceinline__ float2 upk2(ull v) {
    float lo, hi;
    asm("mov.b64 {%0, %1}, %2;" : "=f"(lo), "=f"(hi) : "l"(v));
    return make_float2(lo, hi);
}

/* ---------------- gate primitives ---------------------------------------- */
__device__ __forceinline__ void gate_ry(float2* st, int p, int bp, float c, float s) {
    int ml = (1 << bp) - 1;
    int i0 = ((p & ~ml) << 1) | (p & ml);
    int i1 = i0 | (1 << bp);
    float2 a0 = st[i0], a1 = st[i1];
    st[i0] = make_float2(c * a0.x - s * a1.x, c * a0.y - s * a1.y);
    st[i1] = make_float2(s * a0.x + c * a1.x, s * a0.y + c * a1.y);
}
__device__ __forceinline__ void gate_crx(float2* st, int p, int bc, int bt, float c, float s) {
    int lo = bc < bt ? bc : bt;
    int hi = bc < bt ? bt : bc;
    int mlo = (1 << lo) - 1, mhi = (1 << hi) - 1;
    int m = p;
    m = ((m & ~mlo) << 1) | (m & mlo);
    m = ((m & ~mhi) << 1) | (m & mhi);
    int i0 = m | (1 << bc);
    int i1 = i0 | (1 << bt);
    float2 a0 = st[i0], a1 = st[i1];
    st[i0] = make_float2(c * a0.x + s * a1.y, c * a0.y - s * a1.x);
    st[i1] = make_float2(s * a0.y + c * a1.x, -s * a0.x + c * a1.y);
}
/* gate schedule: per 32-gate layer: 8 RY (q=0..7), 8 CRX (ctrl=7..0, tgt=c+1),
   8 RY, 8 CRX (ctrl in [7,0..6], tgt=c-1). Same mapping that passed in R1. */
__device__ __forceinline__ void gate_geom(int gl, int& type, int& bp, int& bc, int& bt) {
    if ((gl & 8) == 0) {
        type = 0;
        bp = 7 - (gl & 7);
    } else {
        type = 1;
        int j = gl & 7, ctrl, tgt;
        if (gl < 16) { ctrl = 7 - j;                  tgt = (ctrl + 1) & 7; }
        else         { ctrl = (j == 0) ? 7 : (j - 1); tgt = (ctrl + 7) & 7; }
        bc = 7 - ctrl; bt = 7 - tgt;
    }
}

/* =============== mega-kernel: everything except FF2 ====================== */
__global__ void __launch_bounds__(512) k_mega(
    const int*   __restrict__ x,
    const float* __restrict__ embW,
    const float* __restrict__ e2rW,
    const float* __restrict__ e2rb,
    const float* __restrict__ poly,
    const float* __restrict__ mix,
    const float* __restrict__ qff,
    const float* __restrict__ ff1W,
    const float* __restrict__ ff1b)
{
    int b = blockIdx.x, tid = threadIdx.x;

    __shared__ __align__(16) char u_raw[NW * EMB * 4];   /* 32 KB union */
    float*  emb = reinterpret_cast<float*>(u_raw);       /* [NW][EMB]   */
    float2* stw = reinterpret_cast<float2*>(u_raw);      /* [NW][DIM]   */
    __shared__ float2 cs[NW][NROTS];                     /* 8 KB  */
    __shared__ float2 csf[32];
    __shared__ float2 coeffs[NW];
    __shared__ float2 work[DIM];
    __shared__ float2 acc[DIM];
    __shared__ int    toks[NW];
    __shared__ float  red[16];
    __shared__ float  ex[NM];
    __shared__ float  inv_nrm;
    __shared__ float3 wred[4];

    if (tid < NW) toks[tid] = x[b * NW + tid];
    if (tid == 0) {
        float ssum = 0.f;
        for (int w = 0; w < NW; w++) {
            float re = mix[2 * w], im = mix[2 * w + 1];
            ssum += sqrtf(re * re + im * im);
        }
        float inv = 1.0f / fmaxf(ssum, 1e-12f);
        for (int w = 0; w < NW; w++)
            coeffs[w] = make_float2(mix[2 * w] * inv, mix[2 * w + 1] * inv);
    }
    if (tid < 32) {
        float p = qff[tid];
        csf[tid] = make_float2(cosf(0.5f * p), sinf(0.5f * p));
    }
    __syncthreads();

    /* stage 16 embedding rows into shared */
    for (int idx = tid; idx < NW * (EMB / 4); idx += 512) {
        int w = idx >> 7, k4 = idx & 127;
        reinterpret_cast<float4*>(emb)[(w << 7) + k4] =
            reinterpret_cast<const float4*>(embW + (size_t)toks[w] * EMB)[k4];
    }
    __syncthreads();

    /* wparams + cos/sin: thread t -> rot r = t>>3, words (t&7) and (t&7)+8 */
    {
        int r = tid >> 3, wp = tid & 7;
        const float4* wr = reinterpret_cast<const float4*>(e2rW + (size_t)r * EMB);
        const float4* e0 = reinterpret_cast<const float4*>(emb + wp * EMB);
        const float4* e1 = reinterpret_cast<const float4*>(emb + (wp + 8) * EMB);
        float bias = e2rb[r];
        float a0 = bias, a1 = bias;
#pragma unroll 4
        for (int kk = 0; kk < EMB / 4; kk++) {
            float4 wv = __ldg(&wr[kk]);
            float4 v0 = e0[kk];
            float4 v1 = e1[kk];
            a0 += wv.x * v0.x + wv.y * v0.y + wv.z * v0.z + wv.w * v0.w;
            a1 += wv.x * v1.x + wv.y * v1.y + wv.z * v1.z + wv.w * v1.w;
        }
        cs[wp][r]     = make_float2(cosf(0.5f * a0), sinf(0.5f * a0));
        cs[wp + 8][r] = make_float2(cosf(0.5f * a1), sinf(0.5f * a1));
    }
    float p0 = poly[0], p1 = poly[1], p2 = poly[2], p3 = poly[3];

    __syncthreads();  /* wparams done; emb region now reusable as stw */

    if (tid < DIM) {
        bool z = (tid == 0);
        work[tid] = z ? make_float2(1.f, 0.f) : make_float2(0.f, 0.f);
        acc[tid]  = z ? make_float2(p0, 0.f)  : make_float2(0.f, 0.f);
    }
    __syncthreads();

    /* ---- degree loop: 3 × (broadcast, 64 gates on 16 circuits, mix) ---- */
    for (int d = 1; d <= 3; d++) {
        float pd = (d == 1) ? p1 : ((d == 2) ? p2 : p3);

        /* broadcast work into all 16 circuit states */
#pragma unroll
        for (int k = 0; k < 8; k++) {
            int item = tid + k * 512;
            int w = item >> 8, i = item & 255;
            stw[w * DIM + i] = work[i];
        }
        __syncthreads();

        for (int g = 0; g < 64; g++) {
            int gl = g & 31;
            int type, bp, bc, bt;
            gate_geom(gl, type, bp, bc, bt);
            if (type == 0) {
#pragma unroll
                for (int k = 0; k < 4; k++) {          /* 2048 RY pair-updates */
                    int item = tid + k * 512;
                    int w = item >> 7, p = item & 127;
                    float2 c2 = cs[w][g];
                    gate_ry(stw + w * DIM, p, bp, c2.x, c2.y);
                }
            } else {
#pragma unroll
                for (int k = 0; k < 2; k++) {          /* 1024 CRX pair-updates */
                    int item = tid + k * 512;
                    int w = item >> 6, p = item & 63;
                    float2 c2 = cs[w][g];
                    gate_crx(stw + w * DIM, p, bc, bt, c2.x, c2.y);
                }
            }
            __syncthreads();
        }

        /* word mix + poly accumulate */
        if (tid < DIM) {
            float2 s = make_float2(0.f, 0.f);
#pragma unroll
            for (int w = 0; w < NW; w++) {
                float2 cw = coeffs[w];
                float2 v  = stw[w * DIM + tid];
                s.x += cw.x * v.x - cw.y * v.y;
                s.y += cw.x * v.y + cw.y * v.x;
            }
            work[tid] = s;
            float2 a = acc[tid];
            a.x += pd * s.x; a.y += pd * s.y;
            acc[tid] = a;
        }
        __syncthreads();
    }

    /* ---- normalize ---- */
    float psum = fabsf(p0) + fabsf(p1) + fabsf(p2) + fabsf(p3);
    float inv1 = 1.0f / psum;
    float2 a = make_float2(0.f, 0.f);
    float v = 0.f;
    if (tid < DIM) {
        a = acc[tid];
        a.x *= inv1; a.y *= inv1;
        v = a.x * a.x + a.y * a.y;
    }
    for (int off = 16; off; off >>= 1) v += __shfl_xor_sync(0xffffffffu, v, off);
    if ((tid & 31) == 0) red[tid >> 5] = v;
    __syncthreads();
    if (tid == 0) {
        float s = 0.f;
        for (int k = 0; k < 16; k++) s += red[k];
        float nm = sqrtf(s);
        g_fp[b] = nm;
        inv_nrm = 1.0f / fmaxf(nm, 1e-12f);
    }
    __syncthreads();
    float2* stf = stw;   /* reuse first 2 KB */
    if (tid < DIM) stf[tid] = make_float2(a.x * inv_nrm, a.y * inv_nrm);
    __syncthreads();

    /* ---- final 32-gate circuit (single state) ---- */
    for (int g = 0; g < 32; g++) {
        int type, bp, bc, bt;
        gate_geom(g, type, bp, bc, bt);
        if (type == 0) {
            if (tid < 128) gate_ry(stf, tid, bp, csf[g].x, csf[g].y);
        } else {
            if (tid < 64) gate_crx(stf, tid, bc, bt, csf[g].x, csf[g].y);
        }
        __syncthreads();
    }

    /* ---- Pauli X/Y/Z expectations ---- */
    int lane = tid & 31, wrp = tid >> 5;
    for (int w = 0; w < NQ; w++) {
        float cre = 0.f, cim = 0.f, zz = 0.f;
        if (tid < 128) {
            int bp = 7 - w;
            int ml = (1 << bp) - 1;
            int i0 = ((tid & ~ml) << 1) | (tid & ml);
            int i1 = i0 | (1 << bp);
            float2 q0 = stf[i0], q1 = stf[i1];
            cre = q0.x * q1.x + q0.y * q1.y;
            cim = q0.x * q1.y - q0.y * q1.x;
            zz  = q0.x * q0.x + q0.y * q0.y - q1.x * q1.x - q1.y * q1.y;
        }
        for (int off = 16; off; off >>= 1) {
            cre += __shfl_xor_sync(0xffffffffu, cre, off);
            cim += __shfl_xor_sync(0xffffffffu, cim, off);
            zz  += __shfl_xor_sync(0xffffffffu, zz, off);
        }
        if (lane == 0 && wrp < 4) wred[wrp] = make_float3(cre, cim, zz);
        __syncthreads();
        if (tid == 0) {
            float sr = 0.f, si = 0.f, sz = 0.f;
            for (int k = 0; k < 4; k++) { sr += wred[k].x; si += wred[k].y; sz += wred[k].z; }
            ex[w] = 2.f * sr; ex[8 + w] = 2.f * si; ex[16 + w] = sz;
        }
        __syncthreads();
    }

    /* ---- FF1 + ReLU (one output per thread) ---- */
    {
        float s = ff1b[tid];
#pragma unroll
        for (int m = 0; m < NM; m++) s += ex[m] * ff1W[tid * NM + m];
        g_h[b * EMB + tid] = fmaxf(s, 0.f);
    }
}

/* ---------- FF2: op = h @ ff2W^T + b  (HBM-bound; packed f32x2) ---------- */
__global__ void __launch_bounds__(128) k_ff2(const float* __restrict__ ff2W,
                                             const float* __restrict__ ff2b,
                                             float* __restrict__ out,
                                             int write_mean) {
    if (blockIdx.x == 0 && threadIdx.x == 0 && write_mean) {
        float s = 0.f;
        for (int b = 0; b < BATCH; b++) s += g_fp[b];
        out[(size_t)BATCH * VOCAB] = s * (1.0f / BATCH);
    }

    /* hs2[kp][b] = packed (h[b][2kp], h[b][2kp+1]) : 256*16 ull = 32 KB */
    __shared__ ull hs2[256 * 16];
    int tid = threadIdx.x;
    for (int idx = tid; idx < 256 * 16; idx += 128) {
        int kp = idx >> 4, b = idx & 15;
        float2 hv = *reinterpret_cast<const float2*>(&g_h[b * EMB + 2 * kp]);
        reinterpret_cast<float2*>(hs2)[idx] = hv;
    }
    __syncthreads();

    int v0 = blockIdx.x * 256 + tid;
    int v1 = v0 + 128;
    bool ok0 = v0 < VOCAB, ok1 = v1 < VOCAB;
    const ulonglong2* w0p =
        reinterpret_cast<const ulonglong2*>(ff2W + (size_t)(ok0 ? v0 : 0) * EMB);
    const ulonglong2* w1p =
        reinterpret_cast<const ulonglong2*>(ff2W + (size_t)(ok1 ? v1 : 0) * EMB);

    ull acc0[16], acc1[16];
#pragma unroll
    for (int b = 0; b < 16; b++) { acc0[b] = 0ull; acc1[b] = 0ull; }

    for (int ki = 0; ki < 128; ki++) {           /* 4 k per iter (2 pairs) */
        ulonglong2 wa = w0p[ki];
        ulonglong2 wb = w1p[ki];
        const ull* h0 = &hs2[(ki * 2) * 16];
        const ull* h1 = h0 + 16;
#pragma unroll
        for (int b = 0; b < 16; b += 2) {
            ulonglong2 hb0 = *reinterpret_cast<const ulonglong2*>(h0 + b);
            ulonglong2 hb1 = *reinterpret_cast<const ulonglong2*>(h1 + b);
            acc0[b]     = fma2(wa.x, hb0.x, acc0[b]);
            acc0[b + 1] = fma2(wa.x, hb0.y, acc0[b + 1]);
            acc0[b]     = fma2(wa.y, hb1.x, acc0[b]);
            acc0[b + 1] = fma2(wa.y, hb1.y, acc0[b + 1]);
            acc1[b]     = fma2(wb.x, hb0.x, acc1[b]);
            acc1[b + 1] = fma2(wb.x, hb0.y, acc1[b + 1]);
            acc1[b]     = fma2(wb.y, hb1.x, acc1[b]);
            acc1[b + 1] = fma2(wb.y, hb1.y, acc1[b + 1]);
        }
    }

    float bias0 = ok0 ? ff2b[v0] : 0.f;
    float bias1 = ok1 ? ff2b[v1] : 0.f;
#pragma unroll
    for (int b = 0; b < 16; b++) {
        float2 p = upk2(acc0[b]);
        if (ok0) out[(size_t)b * VOCAB + v0] = p.x + p.y + bias0;
        float2 q = upk2(acc1[b]);
        if (ok1) out[(size_t)b * VOCAB + v1] = q.x + q.y + bias1;
    }
}

/* ---------------- launch ------------------------------------------------- */
extern "C" void kernel_launch(void* const* d_in, const int* in_sizes, int n_in,
                              void* d_out, int out_size) {
    const int*   x    = (const int*)  d_in[0];
    const float* embW = (const float*)d_in[1];
    const float* e2rW = (const float*)d_in[2];
    const float* e2rb = (const float*)d_in[3];
    const float* poly = (const float*)d_in[4];
    const float* mix  = (const float*)d_in[5];
    const float* qff  = (const float*)d_in[6];
    const float* ff1W = (const float*)d_in[7];
    const float* ff1b = (const float*)d_in[8];
    const float* ff2W = (const float*)d_in[9];
    const float* ff2b = (const float*)d_in[10];
    float* out = (float*)d_out;

    int write_mean = (out_size > BATCH * VOCAB) ? 1 : 0;

    k_mega<<<BATCH, 512>>>(x, embW, e2rW, e2rb, poly, mix, qff, ff1W, ff1b);
    k_ff2<<<(VOCAB + 255) / 256, 128>>>(ff2W, ff2b, out, write_mean);
}

// round 5
// speedup vs baseline: 1.7650x; 1.7650x over previous
#include <cuda_runtime.h>
#include <cstdint>

#define NQ     8
#define DIM    256
#define NW     16
#define BATCH  16
#define NROTS  64
#define EMB    512
#define VOCAB  50257
#define NM     24

typedef unsigned long long ull;

/* ---------------- scratch (device globals) ------------------------------- */
__device__ float  g_fp[BATCH];
__device__ float  g_h[BATCH * EMB];
__device__ float2 g_cs[BATCH * NW * NROTS];   /* cos/sin of wparams */

/* ---------------- packed f32x2 helpers ----------------------------------- */
__device__ __forceinline__ ull fma2(ull a, ull b, ull c) {
    ull d;
    asm("fma.rn.f32x2 %0, %1, %2, %3;" : "=l"(d) : "l"(a), "l"(b), "l"(c));
    return d;
}
__device__ __forceinline__ float2 upk2(ull v) {
    float lo, hi;
    asm("mov.b64 {%0, %1}, %2;" : "=f"(lo), "=f"(hi) : "l"(v));
    return make_float2(lo, hi);
}

/* ============ warp-level statevector gates (amp i = lane*8 + r) ==========
   bit 0..2 of i = register index r; bit 3..7 = lane bits 0..4.             */
__device__ __forceinline__ float2 shfl_xor_f2(float2 v, int m) {
    float2 r;
    r.x = __shfl_xor_sync(0xffffffffu, v.x, m);
    r.y = __shfl_xor_sync(0xffffffffu, v.y, m);
    return r;
}

template<int BP>
__device__ __forceinline__ void ry_reg(float2* v, float c, float s) {
#pragma unroll
    for (int r0 = 0; r0 < 8; r0++) {
        if (r0 & (1 << BP)) continue;
        const int r1 = r0 | (1 << BP);
        float2 a0 = v[r0], a1 = v[r1];
        v[r0] = make_float2(c * a0.x - s * a1.x, c * a0.y - s * a1.y);
        v[r1] = make_float2(s * a0.x + c * a1.x, s * a0.y + c * a1.y);
    }
}
template<int LB>
__device__ __forceinline__ void ry_lane(float2* v, float c, float s, int lane) {
    float ss = ((lane >> LB) & 1) ? s : -s;
#pragma unroll
    for (int r = 0; r < 8; r++) {
        float2 p = shfl_xor_f2(v[r], 1 << LB);
        v[r].x = c * v[r].x + ss * p.x;
        v[r].y = c * v[r].y + ss * p.y;
    }
}
/* CRX update (symmetric in both pair halves): v' = (c*v.x + s*p.y, c*v.y - s*p.x) */
template<int BC, int BT>
__device__ __forceinline__ void crx_rr(float2* v, float c, float s) {
#pragma unroll
    for (int r0 = 0; r0 < 8; r0++) {
        if (!(r0 & (1 << BC)) || (r0 & (1 << BT))) continue;
        const int r1 = r0 | (1 << BT);
        float2 a0 = v[r0], a1 = v[r1];
        v[r0] = make_float2(c * a0.x + s * a1.y, c * a0.y - s * a1.x);
        v[r1] = make_float2(s * a0.y + c * a1.x, -s * a0.x + c * a1.y);
    }
}
template<int LC, int BT>
__device__ __forceinline__ void crx_lr(float2* v, float c, float s, int lane) {
    if ((lane >> LC) & 1) {
#pragma unroll
        for (int r0 = 0; r0 < 8; r0++) {
            if (r0 & (1 << BT)) continue;
            const int r1 = r0 | (1 << BT);
            float2 a0 = v[r0], a1 = v[r1];
            v[r0] = make_float2(c * a0.x + s * a1.y, c * a0.y - s * a1.x);
            v[r1] = make_float2(s * a0.y + c * a1.x, -s * a0.x + c * a1.y);
        }
    }
}
template<int BC, int LT>
__device__ __forceinline__ void crx_rl(float2* v, float c, float s) {
#pragma unroll
    for (int r = 0; r < 8; r++) {
        if (!(r & (1 << BC))) continue;
        float2 p = shfl_xor_f2(v[r], 1 << LT);
        float2 a = v[r];
        v[r].x = c * a.x + s * p.y;
        v[r].y = c * a.y - s * p.x;
    }
}
template<int LC, int LT>
__device__ __forceinline__ void crx_ll(float2* v, float c, float s, int lane) {
    bool act = (lane >> LC) & 1;
#pragma unroll
    for (int r = 0; r < 8; r++) {
        float2 p = shfl_xor_f2(v[r], 1 << LT);
        if (act) {
            float2 a = v[r];
            v[r].x = c * a.x + s * p.y;
            v[r].y = c * a.y - s * p.x;
        }
    }
}

/* one 32-gate ansatz layer; cs = this circuit's angles for the layer */
__device__ __forceinline__ void sim_layer(float2* v, const float2* cs, int lane) {
    float2 g;
    g = cs[0];  ry_lane<4>(v, g.x, g.y, lane);
    g = cs[1];  ry_lane<3>(v, g.x, g.y, lane);
    g = cs[2];  ry_lane<2>(v, g.x, g.y, lane);
    g = cs[3];  ry_lane<1>(v, g.x, g.y, lane);
    g = cs[4];  ry_lane<0>(v, g.x, g.y, lane);
    g = cs[5];  ry_reg<2>(v, g.x, g.y);
    g = cs[6];  ry_reg<1>(v, g.x, g.y);
    g = cs[7];  ry_reg<0>(v, g.x, g.y);
    g = cs[8];  crx_rl<0, 4>(v, g.x, g.y);
    g = cs[9];  crx_rr<1, 0>(v, g.x, g.y);
    g = cs[10]; crx_rr<2, 1>(v, g.x, g.y);
    g = cs[11]; crx_lr<0, 2>(v, g.x, g.y, lane);
    g = cs[12]; crx_ll<1, 0>(v, g.x, g.y, lane);
    g = cs[13]; crx_ll<2, 1>(v, g.x, g.y, lane);
    g = cs[14]; crx_ll<3, 2>(v, g.x, g.y, lane);
    g = cs[15]; crx_ll<4, 3>(v, g.x, g.y, lane);
    g = cs[16]; ry_lane<4>(v, g.x, g.y, lane);
    g = cs[17]; ry_lane<3>(v, g.x, g.y, lane);
    g = cs[18]; ry_lane<2>(v, g.x, g.y, lane);
    g = cs[19]; ry_lane<1>(v, g.x, g.y, lane);
    g = cs[20]; ry_lane<0>(v, g.x, g.y, lane);
    g = cs[21]; ry_reg<2>(v, g.x, g.y);
    g = cs[22]; ry_reg<1>(v, g.x, g.y);
    g = cs[23]; ry_reg<0>(v, g.x, g.y);
    g = cs[24]; crx_rr<0, 1>(v, g.x, g.y);
    g = cs[25]; crx_lr<4, 0>(v, g.x, g.y, lane);
    g = cs[26]; crx_ll<3, 4>(v, g.x, g.y, lane);
    g = cs[27]; crx_ll<2, 3>(v, g.x, g.y, lane);
    g = cs[28]; crx_ll<1, 2>(v, g.x, g.y, lane);
    g = cs[29]; crx_ll<0, 1>(v, g.x, g.y, lane);
    g = cs[30]; crx_rl<2, 0>(v, g.x, g.y);
    g = cs[31]; crx_rr<1, 2>(v, g.x, g.y);
}

/* --------- kernel 1: wparams = emb @ e2rW^T + b, then cos/sin ------------ */
__global__ void k_wparams(const int* __restrict__ x,
                          const float* __restrict__ embW,
                          const float* __restrict__ e2rW,
                          const float* __restrict__ e2rb) {
    int bw = blockIdx.x, tid = threadIdx.x;      /* 64 threads */
    __shared__ float emb[EMB];
    int tok = x[bw];
    for (int k = tid; k < EMB; k += 64)
        emb[k] = embW[(size_t)tok * EMB + k];
    __syncthreads();
    const float4* wr = reinterpret_cast<const float4*>(e2rW + (size_t)tid * EMB);
    const float4* es = reinterpret_cast<const float4*>(emb);
    float acc = e2rb[tid];
#pragma unroll 8
    for (int kk = 0; kk < EMB / 4; kk++) {
        float4 a = __ldg(&wr[kk]);
        float4 b = es[kk];
        acc += a.x * b.x + a.y * b.y + a.z * b.z + a.w * b.w;
    }
    g_cs[bw * NROTS + tid] = make_float2(cosf(0.5f * acc), sinf(0.5f * acc));
}

/* --------- kernel 2: mega (sim 3 degrees + finalize + measure + FF1) ----- */
__global__ void __launch_bounds__(512) k_mega(
    const float* __restrict__ poly,
    const float* __restrict__ mix,
    const float* __restrict__ qff,
    const float* __restrict__ ff1W,
    const float* __restrict__ ff1b)
{
    int b = blockIdx.x, tid = threadIdx.x;
    int w = tid >> 5, lane = tid & 31;

    __shared__ float2 st_sh[NW * DIM];   /* 32 KB */
    __shared__ float2 cs_sh[NW * NROTS]; /* 8 KB */
    __shared__ float2 work[DIM];
    __shared__ float2 acc[DIM];
    __shared__ float2 coeffs[NW];
    __shared__ float2 csf[32];
    __shared__ float  red[8];
    __shared__ float  ex[NM];
    __shared__ float  inv_nrm_sh;

    for (int i = tid; i < NW * NROTS; i += 512)
        cs_sh[i] = g_cs[b * NW * NROTS + i];
    if (tid == 0) {
        float ssum = 0.f;
        for (int k = 0; k < NW; k++) {
            float re = mix[2 * k], im = mix[2 * k + 1];
            ssum += sqrtf(re * re + im * im);
        }
        float inv = 1.0f / fmaxf(ssum, 1e-12f);
        for (int k = 0; k < NW; k++)
            coeffs[k] = make_float2(mix[2 * k] * inv, mix[2 * k + 1] * inv);
    }
    if (tid < 32) {
        float p = qff[tid];
        csf[tid] = make_float2(cosf(0.5f * p), sinf(0.5f * p));
    }
    float p0 = poly[0], p1 = poly[1], p2 = poly[2], p3 = poly[3];
    if (tid < DIM) {
        bool z = (tid == 0);
        work[tid] = z ? make_float2(1.f, 0.f) : make_float2(0.f, 0.f);
        acc[tid]  = z ? make_float2(p0, 0.f)  : make_float2(0.f, 0.f);
    }
    __syncthreads();

#pragma unroll 1
    for (int d = 1; d <= 3; d++) {
        float pd = (d == 1) ? p1 : ((d == 2) ? p2 : p3);
        float2 v[8];
#pragma unroll
        for (int r = 0; r < 8; r++) v[r] = work[lane * 8 + r];

        sim_layer(v, cs_sh + w * NROTS, lane);
        sim_layer(v, cs_sh + w * NROTS + 32, lane);

#pragma unroll
        for (int r = 0; r < 8; r++) st_sh[w * DIM + lane * 8 + r] = v[r];
        __syncthreads();

        if (tid < DIM) {
            float2 s = make_float2(0.f, 0.f);
#pragma unroll
            for (int w2 = 0; w2 < NW; w2++) {
                float2 cw = coeffs[w2];
                float2 u  = st_sh[w2 * DIM + tid];
                s.x += cw.x * u.x - cw.y * u.y;
                s.y += cw.x * u.y + cw.y * u.x;
            }
            work[tid] = s;
            float2 a = acc[tid];
            a.x += pd * s.x; a.y += pd * s.y;
            acc[tid] = a;
        }
        __syncthreads();
    }

    /* normalize */
    float psum = fabsf(p0) + fabsf(p1) + fabsf(p2) + fabsf(p3);
    float inv1 = 1.0f / psum;
    float2 a2 = make_float2(0.f, 0.f);
    float nv = 0.f;
    if (tid < DIM) {
        a2 = acc[tid];
        a2.x *= inv1; a2.y *= inv1;
        nv = a2.x * a2.x + a2.y * a2.y;
    }
    for (int off = 16; off; off >>= 1) nv += __shfl_xor_sync(0xffffffffu, nv, off);
    if (tid < DIM && lane == 0) red[w] = nv;
    __syncthreads();
    if (tid == 0) {
        float s = 0.f;
        for (int k = 0; k < 8; k++) s += red[k];
        float nm = sqrtf(s);
        g_fp[b] = nm;
        inv_nrm_sh = 1.0f / fmaxf(nm, 1e-12f);
    }
    __syncthreads();
    float inv2 = inv_nrm_sh;
    if (tid < DIM) st_sh[tid] = make_float2(a2.x * inv2, a2.y * inv2);
    __syncthreads();

    /* final 32-gate circuit + measurement: warp 0 only */
    if (w == 0) {
        float2 v[8];
#pragma unroll
        for (int r = 0; r < 8; r++) v[r] = st_sh[lane * 8 + r];
        sim_layer(v, csf, lane);

        for (int q = 0; q < NQ; q++) {
            int bp = 7 - q;
            float cre = 0.f, cim = 0.f, zz = 0.f;
            if (bp >= 3) {
                int lb = bp - 3;
                int tb = (lane >> lb) & 1;
#pragma unroll
                for (int r = 0; r < 8; r++) {
                    float2 p = shfl_xor_f2(v[r], 1 << lb);
                    float nn = v[r].x * v[r].x + v[r].y * v[r].y;
                    if (tb == 0) {
                        cre += v[r].x * p.x + v[r].y * p.y;
                        cim += v[r].x * p.y - v[r].y * p.x;
                        zz  += nn;
                    } else {
                        zz  -= nn;
                    }
                }
            } else {
#pragma unroll
                for (int r0 = 0; r0 < 8; r0++) {
                    if (r0 & (1 << bp)) continue;
                    int r1 = r0 | (1 << bp);
                    cre += v[r0].x * v[r1].x + v[r0].y * v[r1].y;
                    cim += v[r0].x * v[r1].y - v[r0].y * v[r1].x;
                    zz  += v[r0].x * v[r0].x + v[r0].y * v[r0].y
                         - v[r1].x * v[r1].x - v[r1].y * v[r1].y;
                }
            }
            for (int off = 16; off; off >>= 1) {
                cre += __shfl_xor_sync(0xffffffffu, cre, off);
                cim += __shfl_xor_sync(0xffffffffu, cim, off);
                zz  += __shfl_xor_sync(0xffffffffu, zz, off);
            }
            if (lane == 0) { ex[q] = 2.f * cre; ex[8 + q] = 2.f * cim; ex[16 + q] = zz; }
        }
    }
    __syncthreads();

    /* FF1 + ReLU */
    {
        float s = ff1b[tid];
#pragma unroll
        for (int m = 0; m < NM; m++) s += ex[m] * ff1W[tid * NM + m];
        g_h[b * EMB + tid] = fmaxf(s, 0.f);
    }
}

/* --------- kernel 3: FF2 op = h @ ff2W^T + b  (HBM stream) --------------- */
__global__ void __launch_bounds__(256, 4) k_ff2(const float* __restrict__ ff2W,
                                                const float* __restrict__ ff2b,
                                                float* __restrict__ out,
                                                int write_mean) {
    if (blockIdx.x == 0 && threadIdx.x == 0 && write_mean) {
        float s = 0.f;
        for (int b = 0; b < BATCH; b++) s += g_fp[b];
        out[(size_t)BATCH * VOCAB] = s * (1.0f / BATCH);
    }

    __shared__ ull hs2[256 * 16];        /* [kpair][batch] packed h */
    int tid = threadIdx.x;
    for (int idx = tid; idx < 256 * 16; idx += 256) {
        int kp = idx >> 4, b = idx & 15;
        float2 hv = *reinterpret_cast<const float2*>(&g_h[b * EMB + 2 * kp]);
        reinterpret_cast<float2*>(hs2)[idx] = hv;
    }
    __syncthreads();

    int v = blockIdx.x * 256 + tid;
    bool ok = v < VOCAB;
    const ulonglong2* wp =
        reinterpret_cast<const ulonglong2*>(ff2W + (size_t)(ok ? v : 0) * EMB);

    ull acc[16];
#pragma unroll
    for (int b = 0; b < 16; b++) acc[b] = 0ull;

#pragma unroll 1
    for (int kb = 0; kb < 128; kb += 4) {
        ulonglong2 wv0 = wp[kb + 0];
        ulonglong2 wv1 = wp[kb + 1];
        ulonglong2 wv2 = wp[kb + 2];
        ulonglong2 wv3 = wp[kb + 3];
#pragma unroll
        for (int u = 0; u < 4; u++) {
            ulonglong2 wv = (u == 0) ? wv0 : (u == 1) ? wv1 : (u == 2) ? wv2 : wv3;
            const ull* h0 = &hs2[((kb + u) * 2) * 16];
            const ull* h1 = h0 + 16;
#pragma unroll
            for (int b = 0; b < 16; b += 2) {
                ulonglong2 hb0 = *reinterpret_cast<const ulonglong2*>(h0 + b);
                ulonglong2 hb1 = *reinterpret_cast<const ulonglong2*>(h1 + b);
                acc[b]     = fma2(wv.x, hb0.x, acc[b]);
                acc[b + 1] = fma2(wv.x, hb0.y, acc[b + 1]);
                acc[b]     = fma2(wv.y, hb1.x, acc[b]);
                acc[b + 1] = fma2(wv.y, hb1.y, acc[b + 1]);
            }
        }
    }

    if (ok) {
        float bias = ff2b[v];
#pragma unroll
        for (int b = 0; b < 16; b++) {
            float2 p = upk2(acc[b]);
            out[(size_t)b * VOCAB + v] = p.x + p.y + bias;
        }
    }
}

/* ---------------- launch ------------------------------------------------- */
extern "C" void kernel_launch(void* const* d_in, const int* in_sizes, int n_in,
                              void* d_out, int out_size) {
    const int*   x    = (const int*)  d_in[0];
    const float* embW = (const float*)d_in[1];
    const float* e2rW = (const float*)d_in[2];
    const float* e2rb = (const float*)d_in[3];
    const float* poly = (const float*)d_in[4];
    const float* mix  = (const float*)d_in[5];
    const float* qff  = (const float*)d_in[6];
    const float* ff1W = (const float*)d_in[7];
    const float* ff1b = (const float*)d_in[8];
    const float* ff2W = (const float*)d_in[9];
    const float* ff2b = (const float*)d_in[10];
    float* out = (float*)d_out;

    int write_mean = (out_size > BATCH * VOCAB) ? 1 : 0;

    k_wparams<<<BATCH * NW, 64>>>(x, embW, e2rW, e2rb);
    k_mega<<<BATCH, 512>>>(poly, mix, qff, ff1W, ff1b);
    k_ff2<<<(VOCAB + 255) / 256, 256>>>(ff2W, ff2b, out, write_mean);
}